// round 4
// baseline (speedup 1.0000x reference)
#include <cuda_runtime.h>
#include <stdint.h>
#include <math.h>

// Problem constants (fixed by dataset)
#define MAXN     100000
#define FIN      128
#define HID      64
#define NBW      ((MAXN + 31) / 32)   // bitmap words (12.5 KB each)
#define MAXSLOTS 16384                // |V1| bound (actual ~2.1k)
#define STRIDE   160                  // per-slot in-edge bound (Poisson(32); P(>90)<1e-10)
#define MAXL2    65536                // layer-2 edge bound (actual ~2k)

// ---------------- static device scratch (zero at entry; tail re-zeroes) -----
__device__ int      d_deg[MAXN];
__device__ float    d_dinv[MAXN];
__device__ unsigned d_isout_bits[NBW];
__device__ unsigned d_need_bits[NBW];
__device__ int      d_slot[MAXN];               // node -> slot (valid iff need bit)
__device__ int      d_slotnode[MAXSLOTS];       // slot -> node
__device__ int      d_cnt[MAXSLOTS];            // per-slot in-edge count
__device__ int      d_adj[(size_t)MAXSLOTS * STRIDE]; // per-slot in-edge sources
__device__ float    d_tval[MAXSLOTS];           // relu(h1)@W2 per slot
__device__ int2     d_l2[MAXL2];                // edges into output nodes
__device__ int      d_nslots;
__device__ int      d_nl2;

__device__ __forceinline__ int test_bit(const unsigned* bits, int i) {
    return (bits[i >> 5] >> (i & 31)) & 1u;
}

// ---------------------------------------------------------------------------
// Mark output nodes (last of each graph, batch sorted); init out[] with bias.
__global__ void k_mark(const int* __restrict__ batch, int N,
                       float* __restrict__ out, const float* __restrict__ b2, int G) {
    int i = blockIdx.x * blockDim.x + threadIdx.x;
    if (i < G) out[i] = b2[0];
    if (i >= N) return;
    bool last = (i == N - 1) || (batch[i] != batch[i + 1]);
    if (last) {
        atomicOr(&d_isout_bits[i >> 5], 1u << (i & 31));
        atomicOr(&d_need_bits[i >> 5], 1u << (i & 31));
        int s = atomicAdd(&d_nslots, 1);
        if (s < MAXSLOTS) { d_slot[i] = s; d_slotnode[s] = i; }
    }
}

// pass1: in-degree histogram (RED) + collect layer-2 edges + build V1 slot set
__device__ __forceinline__ void pass1_one(int sj, int dj) {
    atomicAdd(&d_deg[dj], 1);                       // RED (no return use)
    if (test_bit(d_isout_bits, dj)) {               // 12.5 KB bitmap: L1 hit
        int p = atomicAdd(&d_nl2, 1);
        if (p < MAXL2) d_l2[p] = make_int2(sj, dj);
        unsigned bit = 1u << (sj & 31);
        unsigned old = atomicOr(&d_need_bits[sj >> 5], bit);
        if (!(old & bit)) {                          // winner assigns slot
            int s = atomicAdd(&d_nslots, 1);
            if (s < MAXSLOTS) { d_slot[sj] = s; d_slotnode[s] = sj; }
        }
    }
}

__global__ void k_pass1_v4(const int4* __restrict__ src4, const int4* __restrict__ dst4, int E4) {
    int i = blockIdx.x * blockDim.x + threadIdx.x;
    if (i >= E4) return;
    int4 s = __ldg(&src4[i]);
    int4 d = __ldg(&dst4[i]);
    pass1_one(s.x, d.x);
    pass1_one(s.y, d.y);
    pass1_one(s.z, d.z);
    pass1_one(s.w, d.w);
}
__global__ void k_pass1_s(const int* __restrict__ src, const int* __restrict__ dst, int E) {
    int i = blockIdx.x * blockDim.x + threadIdx.x;
    if (i >= E) return;
    pass1_one(__ldg(&src[i]), __ldg(&dst[i]));
}

// fused: dinv for all nodes (blocks [0,DB)) + bucket matched edges (blocks [DB,..))
__global__ void k_mid_v4(const int* __restrict__ src, const int4* __restrict__ dst4,
                         int E4, int N, int DB) {
    if ((int)blockIdx.x < DB) {
        int i = blockIdx.x * blockDim.x + threadIdx.x;
        if (i < N) d_dinv[i] = rsqrtf((float)(d_deg[i] + 1));
        return;
    }
    int j = (blockIdx.x - DB) * blockDim.x + threadIdx.x;
    if (j >= E4) return;
    int4 d = __ldg(&dst4[j]);
    int base = 4 * j;
    #pragma unroll
    for (int c = 0; c < 4; c++) {
        int dj = (c == 0) ? d.x : (c == 1) ? d.y : (c == 2) ? d.z : d.w;
        if (test_bit(d_need_bits, dj)) {            // L1-resident bitmap probe
            int sl = d_slot[dj];
            int p  = atomicAdd(&d_cnt[sl], 1);
            if (p < STRIDE) d_adj[(size_t)sl * STRIDE + p] = __ldg(&src[base + c]);
        }
    }
}
__global__ void k_mid_s(const int* __restrict__ src, const int* __restrict__ dst,
                        int E, int N, int DB) {
    if ((int)blockIdx.x < DB) {
        int i = blockIdx.x * blockDim.x + threadIdx.x;
        if (i < N) d_dinv[i] = rsqrtf((float)(d_deg[i] + 1));
        return;
    }
    int i = (blockIdx.x - DB) * blockDim.x + threadIdx.x;
    if (i >= E) return;
    int dj = __ldg(&dst[i]);
    if (test_bit(d_need_bits, dj)) {
        int sl = d_slot[dj];
        int p  = atomicAdd(&d_cnt[sl], 1);
        if (p < STRIDE) d_adj[(size_t)sl * STRIDE + p] = __ldg(&src[i]);
    }
}

// block per slot: gather in-edges, layer-1 dense compute, tval; add self term
__global__ void __launch_bounds__(FIN) k_compute(const float* __restrict__ x,
                          const float* __restrict__ W1,
                          const float* __restrict__ b1,
                          const float* __restrict__ W2,
                          const int*   __restrict__ batch,
                          float* __restrict__ out) {
    __shared__ float ysh[FIN];
    __shared__ float redsh[HID];
    int ns = d_nslots; if (ns > MAXSLOTS) ns = MAXSLOTS;
    int t  = threadIdx.x;   // 0..127, feature index
    for (int s = blockIdx.x; s < ns; s += gridDim.x) {
        int v   = d_slotnode[s];
        int cnt = d_cnt[s]; if (cnt > STRIDE) cnt = STRIDE;
        const int* adj = &d_adj[(size_t)s * STRIDE];
        float acc0 = 0.f, acc1 = 0.f;
        int e = 0;
        for (; e + 2 <= cnt; e += 2) {
            int u0 = __ldg(&adj[e]);
            int u1 = __ldg(&adj[e + 1]);
            float w0 = d_dinv[u0], w1 = d_dinv[u1];
            acc0 = fmaf(__ldg(&x[(size_t)u0 * FIN + t]), w0, acc0);
            acc1 = fmaf(__ldg(&x[(size_t)u1 * FIN + t]), w1, acc1);
        }
        if (e < cnt) {
            int u = __ldg(&adj[e]);
            acc0 = fmaf(__ldg(&x[(size_t)u * FIN + t]), d_dinv[u], acc0);
        }
        float dv = d_dinv[v];
        ysh[t] = (acc0 + acc1) * dv + __ldg(&x[(size_t)v * FIN + t]) * dv * dv;
        __syncthreads();
        if (t < HID) {
            float h = b1[t];
            #pragma unroll 16
            for (int k = 0; k < FIN; k++)
                h = fmaf(ysh[k], W1[k * HID + t], h);
            h = fmaxf(h, 0.f);
            redsh[t] = h * W2[t];
        }
        __syncthreads();
        if (t < 32) {
            float p = redsh[t] + redsh[t + 32];
            #pragma unroll
            for (int o = 16; o > 0; o >>= 1)
                p += __shfl_down_sync(0xffffffffu, p, o);
            if (t == 0) {
                d_tval[s] = p;
                if (test_bit(d_isout_bits, v))      // layer-2 self-loop term
                    atomicAdd(&out[batch[v]], p * dv * dv);
            }
        }
        __syncthreads();
    }
}

// block 0: layer-2 edge reduce; all blocks: zero scratch for the next call
__global__ void k_final(const int* __restrict__ batch, float* __restrict__ out) {
    int i = blockIdx.x * blockDim.x + threadIdx.x;
    if (blockIdx.x == 0) {
        int n1 = d_nl2; if (n1 > MAXL2) n1 = MAXL2;
        for (int k = threadIdx.x; k < n1; k += blockDim.x) {
            int2 e = d_l2[k];
            atomicAdd(&out[batch[e.y]],
                      d_tval[d_slot[e.x]] * d_dinv[e.x] * d_dinv[e.y]);
        }
        __syncthreads();
        if (threadIdx.x == 0) { d_nl2 = 0; d_nslots = 0; }
    }
    if (i < MAXN) d_deg[i] = 0;
    if (i < NBW) { d_isout_bits[i] = 0u; d_need_bits[i] = 0u; }
    if (i < MAXSLOTS) d_cnt[i] = 0;
}

// ---------------------------------------------------------------------------
extern "C" void kernel_launch(void* const* d_in, const int* in_sizes, int n_in,
                              void* d_out, int out_size) {
    const float* x     = (const float*)d_in[0];
    const int*   ei    = (const int*)  d_in[1];
    const int*   batch = (const int*)  d_in[2];
    const float* W1    = (const float*)d_in[3];
    const float* b1    = (const float*)d_in[4];
    const float* W2    = (const float*)d_in[5];
    const float* b2    = (const float*)d_in[6];
    float* out = (float*)d_out;

    const int N = in_sizes[2];
    const int E = in_sizes[1] / 2;
    const int G = out_size;

    const int* src = ei;
    const int* dst = ei + E;

    int gN = (N + 255) / 256;

    k_mark<<<gN, 256>>>(batch, N, out, b2, G);

    bool vec_ok = ((E & 3) == 0) &&
                  ((((uintptr_t)src) & 15) == 0) && ((((uintptr_t)dst) & 15) == 0);
    if (vec_ok) {
        int E4  = E / 4;
        int gE4 = (E4 + 255) / 256;
        k_pass1_v4<<<gE4, 256>>>((const int4*)src, (const int4*)dst, E4);
        k_mid_v4  <<<gN + gE4, 256>>>(src, (const int4*)dst, E4, N, gN);
    } else {
        int gE = (E + 255) / 256;
        k_pass1_s<<<gE, 256>>>(src, dst, E);
        k_mid_s  <<<gN + gE, 256>>>(src, dst, E, N, gN);
    }

    k_compute<<<2048, FIN>>>(x, W1, b1, W2, batch, out);
    k_final  <<<gN, 256>>>(batch, out);
}

// round 5
// speedup vs baseline: 1.0842x; 1.0842x over previous
#include <cuda_runtime.h>
#include <stdint.h>
#include <math.h>

// Problem constants (fixed by dataset)
#define MAXN     100000
#define FIN      128
#define HID      64
#define NBW      ((MAXN + 31) / 32)   // bitmap words (12.5 KB each)
#define MAXSLOTS 16384                // |V1| bound (actual ~2.1k)
#define STRIDE   160                  // per-slot in-edge bound (Poisson(32); P(>150) ~ 0)
#define MAXL2    65536                // layer-2 edge bound (actual ~2k)

// ---------------- static device scratch (zero at entry; tail re-zeroes) -----
__device__ int      d_deg[MAXN];
__device__ float    d_dinv[MAXN];
__device__ unsigned d_isout_bits[NBW];
__device__ unsigned d_need_bits[NBW];
__device__ int      d_slot[MAXN];               // node -> slot (valid iff need bit)
__device__ int      d_slotnode[MAXSLOTS];       // slot -> node
__device__ int      d_cnt[MAXSLOTS];            // per-slot in-edge count
__device__ int      d_adj[(size_t)MAXSLOTS * STRIDE]; // per-slot in-edge sources
__device__ float    d_tval[MAXSLOTS];           // relu(h1)@W2 per slot
__device__ int2     d_l2[MAXL2];                // edges into output nodes
__device__ int      d_nslots;
__device__ int      d_nl2;

__device__ __forceinline__ int test_bit(const unsigned* bits, int i) {
    return (bits[i >> 5] >> (i & 31)) & 1u;
}

// ---------------------------------------------------------------------------
// Mark output nodes (last of each graph, batch sorted); init out[] with bias.
__global__ void k_mark(const int* __restrict__ batch, int N,
                       float* __restrict__ out, const float* __restrict__ b2, int G) {
    int i = blockIdx.x * blockDim.x + threadIdx.x;
    if (i < G) out[i] = b2[0];
    if (i >= N) return;
    bool last = (i == N - 1) || (batch[i] != batch[i + 1]);
    if (last) {
        atomicOr(&d_isout_bits[i >> 5], 1u << (i & 31));
        atomicOr(&d_need_bits[i >> 5], 1u << (i & 31));
        int s = atomicAdd(&d_nslots, 1);
        if (s < MAXSLOTS) { d_slot[i] = s; d_slotnode[s] = i; }
    }
}

// pass1: in-degree histogram (RED) + collect layer-2 edges + build V1 slot set
__device__ __forceinline__ void pass1_one(int sj, int dj) {
    atomicAdd(&d_deg[dj], 1);                       // RED (no return use)
    if (test_bit(d_isout_bits, dj)) {               // 12.5 KB bitmap: L1 hit
        int p = atomicAdd(&d_nl2, 1);
        if (p < MAXL2) d_l2[p] = make_int2(sj, dj);
        unsigned bit = 1u << (sj & 31);
        unsigned old = atomicOr(&d_need_bits[sj >> 5], bit);
        if (!(old & bit)) {                          // winner assigns slot
            int s = atomicAdd(&d_nslots, 1);
            if (s < MAXSLOTS) { d_slot[sj] = s; d_slotnode[s] = sj; }
        }
    }
}

__global__ void k_pass1_v4(const int4* __restrict__ src4, const int4* __restrict__ dst4, int E4) {
    int i = blockIdx.x * blockDim.x + threadIdx.x;
    if (i >= E4) return;
    int4 s = __ldg(&src4[i]);
    int4 d = __ldg(&dst4[i]);
    pass1_one(s.x, d.x);
    pass1_one(s.y, d.y);
    pass1_one(s.z, d.z);
    pass1_one(s.w, d.w);
}
__global__ void k_pass1_s(const int* __restrict__ src, const int* __restrict__ dst, int E) {
    int i = blockIdx.x * blockDim.x + threadIdx.x;
    if (i >= E) return;
    pass1_one(__ldg(&src[i]), __ldg(&dst[i]));
}

// fused: dinv for all nodes (blocks [0,DB)) + bucket matched edges (blocks [DB,..))
__global__ void k_mid_v4(const int* __restrict__ src, const int4* __restrict__ dst4,
                         int E4, int N, int DB) {
    if ((int)blockIdx.x < DB) {
        int i = blockIdx.x * blockDim.x + threadIdx.x;
        if (i < N) d_dinv[i] = rsqrtf((float)(d_deg[i] + 1));
        return;
    }
    int j = (blockIdx.x - DB) * blockDim.x + threadIdx.x;
    if (j >= E4) return;
    int4 d = __ldg(&dst4[j]);
    int base = 4 * j;
    #pragma unroll
    for (int c = 0; c < 4; c++) {
        int dj = (c == 0) ? d.x : (c == 1) ? d.y : (c == 2) ? d.z : d.w;
        if (test_bit(d_need_bits, dj)) {            // L1-resident bitmap probe
            int sl = d_slot[dj];
            int p  = atomicAdd(&d_cnt[sl], 1);
            if (p < STRIDE) d_adj[(size_t)sl * STRIDE + p] = __ldg(&src[base + c]);
        }
    }
}
__global__ void k_mid_s(const int* __restrict__ src, const int* __restrict__ dst,
                        int E, int N, int DB) {
    if ((int)blockIdx.x < DB) {
        int i = blockIdx.x * blockDim.x + threadIdx.x;
        if (i < N) d_dinv[i] = rsqrtf((float)(d_deg[i] + 1));
        return;
    }
    int i = (blockIdx.x - DB) * blockDim.x + threadIdx.x;
    if (i >= E) return;
    int dj = __ldg(&dst[i]);
    if (test_bit(d_need_bits, dj)) {
        int sl = d_slot[dj];
        int p  = atomicAdd(&d_cnt[sl], 1);
        if (p < STRIDE) d_adj[(size_t)sl * STRIDE + p] = __ldg(&src[i]);
    }
}

// block per slot: stage adjacency in smem, 8-wide-MLP gather, dense layer-1,
// tval, plus the layer-2 self-loop term.
__global__ void __launch_bounds__(FIN) k_compute(const float* __restrict__ x,
                          const float* __restrict__ W1,
                          const float* __restrict__ b1,
                          const float* __restrict__ W2,
                          const int*   __restrict__ batch,
                          float* __restrict__ out) {
    __shared__ float ysh[FIN];
    __shared__ float redsh[HID];
    __shared__ int   s_u[STRIDE];
    __shared__ float s_w[STRIDE];
    int ns = d_nslots; if (ns > MAXSLOTS) ns = MAXSLOTS;
    int t  = threadIdx.x;   // 0..127, feature index
    for (int s = blockIdx.x; s < ns; s += gridDim.x) {
        int v   = d_slotnode[s];
        int cnt = d_cnt[s]; if (cnt > STRIDE) cnt = STRIDE;
        // stage adj indices + weights (parallel, removes pointer-chase)
        for (int e = t; e < cnt; e += FIN) {
            int u = d_adj[(size_t)s * STRIDE + e];
            s_u[e] = u;
            s_w[e] = d_dinv[u];
        }
        __syncthreads();
        // 8 independent x-row loads in flight per thread (MLP=8)
        float acc0 = 0.f, acc1 = 0.f, acc2 = 0.f, acc3 = 0.f;
        int e = 0;
        for (; e + 8 <= cnt; e += 8) {
            float v0 = __ldg(&x[(size_t)s_u[e+0] * FIN + t]);
            float v1 = __ldg(&x[(size_t)s_u[e+1] * FIN + t]);
            float v2 = __ldg(&x[(size_t)s_u[e+2] * FIN + t]);
            float v3 = __ldg(&x[(size_t)s_u[e+3] * FIN + t]);
            float v4 = __ldg(&x[(size_t)s_u[e+4] * FIN + t]);
            float v5 = __ldg(&x[(size_t)s_u[e+5] * FIN + t]);
            float v6 = __ldg(&x[(size_t)s_u[e+6] * FIN + t]);
            float v7 = __ldg(&x[(size_t)s_u[e+7] * FIN + t]);
            acc0 = fmaf(v0, s_w[e+0], acc0);
            acc1 = fmaf(v1, s_w[e+1], acc1);
            acc2 = fmaf(v2, s_w[e+2], acc2);
            acc3 = fmaf(v3, s_w[e+3], acc3);
            acc0 = fmaf(v4, s_w[e+4], acc0);
            acc1 = fmaf(v5, s_w[e+5], acc1);
            acc2 = fmaf(v6, s_w[e+6], acc2);
            acc3 = fmaf(v7, s_w[e+7], acc3);
        }
        for (; e < cnt; e++)
            acc0 = fmaf(__ldg(&x[(size_t)s_u[e] * FIN + t]), s_w[e], acc0);
        float dv = d_dinv[v];
        ysh[t] = ((acc0 + acc1) + (acc2 + acc3)) * dv
               + __ldg(&x[(size_t)v * FIN + t]) * dv * dv;
        __syncthreads();
        if (t < HID) {
            float h = b1[t];
            #pragma unroll 16
            for (int k = 0; k < FIN; k++)
                h = fmaf(ysh[k], W1[k * HID + t], h);
            h = fmaxf(h, 0.f);
            redsh[t] = h * W2[t];
        }
        __syncthreads();
        if (t < 32) {
            float p = redsh[t] + redsh[t + 32];
            #pragma unroll
            for (int o = 16; o > 0; o >>= 1)
                p += __shfl_down_sync(0xffffffffu, p, o);
            if (t == 0) {
                d_tval[s] = p;
                if (test_bit(d_isout_bits, v))      // layer-2 self-loop term
                    atomicAdd(&out[batch[v]], p * dv * dv);
            }
        }
        __syncthreads();
    }
}

// block 0: layer-2 edge reduce; all blocks: zero scratch for the next call
__global__ void k_final(const int* __restrict__ batch, float* __restrict__ out) {
    int i = blockIdx.x * blockDim.x + threadIdx.x;
    if (blockIdx.x == 0) {
        int n1 = d_nl2; if (n1 > MAXL2) n1 = MAXL2;
        for (int k = threadIdx.x; k < n1; k += blockDim.x) {
            int2 e = d_l2[k];
            atomicAdd(&out[batch[e.y]],
                      d_tval[d_slot[e.x]] * d_dinv[e.x] * d_dinv[e.y]);
        }
        __syncthreads();
        if (threadIdx.x == 0) { d_nl2 = 0; d_nslots = 0; }
    }
    if (i < MAXN) d_deg[i] = 0;
    if (i < NBW) { d_isout_bits[i] = 0u; d_need_bits[i] = 0u; }
    if (i < MAXSLOTS) d_cnt[i] = 0;
}

// ---------------------------------------------------------------------------
extern "C" void kernel_launch(void* const* d_in, const int* in_sizes, int n_in,
                              void* d_out, int out_size) {
    const float* x     = (const float*)d_in[0];
    const int*   ei    = (const int*)  d_in[1];
    const int*   batch = (const int*)  d_in[2];
    const float* W1    = (const float*)d_in[3];
    const float* b1    = (const float*)d_in[4];
    const float* W2    = (const float*)d_in[5];
    const float* b2    = (const float*)d_in[6];
    float* out = (float*)d_out;

    const int N = in_sizes[2];
    const int E = in_sizes[1] / 2;
    const int G = out_size;

    const int* src = ei;
    const int* dst = ei + E;

    int gN = (N + 255) / 256;

    k_mark<<<gN, 256>>>(batch, N, out, b2, G);

    bool vec_ok = ((E & 3) == 0) &&
                  ((((uintptr_t)src) & 15) == 0) && ((((uintptr_t)dst) & 15) == 0);
    if (vec_ok) {
        int E4  = E / 4;
        int gE4 = (E4 + 255) / 256;
        k_pass1_v4<<<gE4, 256>>>((const int4*)src, (const int4*)dst, E4);
        k_mid_v4  <<<gN + gE4, 256>>>(src, (const int4*)dst, E4, N, gN);
    } else {
        int gE = (E + 255) / 256;
        k_pass1_s<<<gE, 256>>>(src, dst, E);
        k_mid_s  <<<gN + gE, 256>>>(src, dst, E, N, gN);
    }

    k_compute<<<2048, FIN>>>(x, W1, b1, W2, batch, out);
    k_final  <<<gN, 256>>>(batch, out);
}